// round 14
// baseline (speedup 1.0000x reference)
#include <cuda_runtime.h>
#include <cstdint>

// Problem constants (fixed by setup_inputs)
#define BS 8
#define M  4096
#define T  32
#define E  65536
#define NROWS (BS * M)          // 32768
#define DEG_CAP 64              // Poisson(16) row degree; P(>64) ~ 1e-20

// Scratch. Device globals start zeroed at module load; agg resets the header
// counts after consuming them, so every replay starts clean. Stale entry
// bytes are never read (bounded by deg) and are always < M.
//
// Per-row 16B header: {u32 cnt; u16 e0,e1,e2,e3; 4B pad} -> one LDG.128 in
// agg yields count + the whole fast-path quad. Entries pos >= 4 go to the
// overflow array at [row*64 + pos] (first 4 slots of each ovf row unused).
__device__ uint4   g_rec[NROWS];                 // headers (512 KB)
__device__ ushort4 g_ovf[NROWS * (DEG_CAP / 4)]; // overflow lists (4 MB)

__device__ __forceinline__ void add4(float4& a, const float4& v) {
    a.x += v.x; a.y += v.y; a.z += v.z; a.w += v.w;
}

// ---------------------------------------------------------------------------
// Kernel 1: append every edge (dups included -> dedup lazily in agg). ONE
// atomic per edge, 2 edges per thread (independent chains, MLP=2).
// A_coo is int32, layout (bs, 2, E) row-major; int2 loads from both streams.
// ---------------------------------------------------------------------------
__global__ void nil_build_kernel(const int* __restrict__ coo,
                                 float* __restrict__ out) {
    unsigned tid = blockIdx.x * blockDim.x + threadIdx.x;  // < BS*E/2
    if (tid == 0) *out = 0.0f;
    unsigned b  = tid >> 15;               // / (E/2)
    unsigned e2 = tid & (E / 2 - 1);       // edge-pair index within batch

    const int2* srcs = reinterpret_cast<const int2*>(coo + (size_t)b * 2 * E);
    const int2* tgts = reinterpret_cast<const int2*>(coo + (size_t)b * 2 * E + E);
    int2 sp = srcs[e2];
    int2 tp = tgts[e2];

    unsigned* cnts = reinterpret_cast<unsigned*>(g_rec);  // cnt @ idx row*4
    unsigned short* hdr = reinterpret_cast<unsigned short*>(g_rec);
    unsigned short* ovf = reinterpret_cast<unsigned short*>(g_ovf);

    unsigned src[2] = {(unsigned)sp.x & (M - 1), (unsigned)sp.y & (M - 1)};
    unsigned tgt[2] = {(unsigned)tp.x & (M - 1), (unsigned)tp.y & (M - 1)};
    unsigned row[2] = {b * M + src[0], b * M + src[1]};
    unsigned pos[2];
    #pragma unroll
    for (int p = 0; p < 2; ++p)            // independent chains back-to-back
        pos[p] = atomicAdd(&cnts[row[p] * 4], 1u);
    #pragma unroll
    for (int p = 0; p < 2; ++p) {
        if (pos[p] < 4)
            hdr[row[p] * 8 + 2 + pos[p]] = (unsigned short)tgt[p];
        else if (pos[p] < DEG_CAP)
            ovf[row[p] * DEG_CAP + pos[p]] = (unsigned short)tgt[p];
    }
}

// ---------------------------------------------------------------------------
// Kernel 2: one warp per FOUR consecutive rows. Lane l = (group g=l/8 -> row
// 4w+g, chunk c=l%8 -> t in [4c,4c+3]) holding acc as float4.
//   acc[t] = yb[b,i,t] (identity) + sum over DISTINCT listed targets j of
//            yb[b,j,t]  (first occurrence wins == jnp .at[].set(1.0))
//   reg   += relu(yb[b,i,t+1] - acc[t]), t in [0,31)
// Fast path: ONE 16B header load gives count + first 4 entries; rows whose
// lanes all satisfy acc >= ynext contribute EXACTLY 0 (y >= 0 -> acc
// monotone) and are done. Live rows (~4%) take a warp-converged slow path:
// transpose acc to lane=t layout, build a 64-bit first-occurrence keep mask
// once via match_any, then gather ALL remaining quads with NO intermediate
// ballots (every list load / gather independent -> one latency chain).
// ---------------------------------------------------------------------------
__global__ void nil_agg_kernel(const float* __restrict__ y,
                               float* __restrict__ out) {
    const unsigned FULL = 0xffffffffu;
    unsigned warp = (blockIdx.x * blockDim.x + threadIdx.x) >> 5; // 0..8191
    unsigned lane = threadIdx.x & 31;
    unsigned g = lane >> 3, c = lane & 7;

    unsigned row0 = warp << 2;        // 4 consecutive rows, same batch (M%4==0)
    unsigned row  = row0 + g;
    unsigned b    = row0 >> 12;       // / M
    const float*  yb  = y + (size_t)b * (M * T);
    const float4* yb4 = reinterpret_cast<const float4*>(yb);

    // ---- front-issue independent loads ----
    uint4 rec = g_rec[row];                            // 16B header, 64B/warp
    float4 self4 = yb4[(size_t)(row & (M - 1)) * (T / 4) + c]; // 512B coalesced

    if (lane < 4)                                      // self-clean counts
        reinterpret_cast<unsigned*>(g_rec)[(row0 + lane) * 4] = 0u;

    int deg = (int)rec.x;
    if (deg > DEG_CAP) deg = DEG_CAP;

    float4 acc = self4;                       // identity term
    // ynext for t=4c..4c+3: (self.y, self.z, self.w, next-lane self.x);
    // c==7's 4th term (t=31) is invalid and masked below.
    float n3 = __shfl_down_sync(FULL, self4.x, 1);

    // ---- quad 0 from header: 4 gathers, one LDG.128 per lane ----
    {
        unsigned e0 = rec.y & 0xFFFFu, e1 = rec.y >> 16;
        unsigned e2 = rec.z & 0xFFFFu, e3 = rec.z >> 16;
        float4 v0 = yb4[e0 * (T / 4) + c];
        float4 v1 = yb4[e1 * (T / 4) + c];
        float4 v2 = yb4[e2 * (T / 4) + c];
        float4 v3 = yb4[e3 * (T / 4) + c];
        bool u1 = (e1 != e0);
        bool u2 = (e2 != e0) & (e2 != e1);
        bool u3 = (e3 != e0) & (e3 != e1) & (e3 != e2);
        if (deg > 0)       add4(acc, v0);
        if (deg > 1 && u1) add4(acc, v1);
        if (deg > 2 && u2) add4(acc, v2);
        if (deg > 3 && u3) add4(acc, v3);
    }

    // ---- liveness: any t in this lane with acc[t] < ynext[t]? ----
    bool live = (acc.x < self4.y) | (acc.y < self4.z) | (acc.z < self4.w) |
                ((c < 7) & (acc.w < n3));
    unsigned pend = __ballot_sync(FULL, live);

    float wsum = 0.0f;                        // meaningful on lane 0 only
    if (pend) {
        // ---- warp-converged slow path, one live row at a time ----
        #pragma unroll
        for (int gg = 0; gg < 4; ++gg) {
            if (!((pend >> (8 * gg)) & 0xFFu)) continue;
            unsigned r_row = row0 + gg;
            unsigned srcw = gg * 8;
            int dg = __shfl_sync(FULL, deg, srcw);
            unsigned w1 = __shfl_sync(FULL, rec.y, srcw);
            unsigned w2 = __shfl_sync(FULL, rec.z, srcw);

            // transpose this row's acc into lane=t layout
            unsigned srcl = srcw + (lane >> 2);
            float a0 = __shfl_sync(FULL, acc.x, srcl);
            float a1 = __shfl_sync(FULL, acc.y, srcl);
            float a2 = __shfl_sync(FULL, acc.z, srcl);
            float a3 = __shfl_sync(FULL, acc.w, srcl);
            unsigned sel = lane & 3;
            float accT = (sel == 0) ? a0 : (sel == 1) ? a1
                       : (sel == 2) ? a2 : a3;

            float selfT = yb[(size_t)(r_row & (M - 1)) * T + lane];
            float ynT = __shfl_down_sync(FULL, selfT, 1);
            bool tv = (lane < 31);

            const unsigned short* ovf =
                reinterpret_cast<const unsigned short*>(g_ovf) +
                (size_t)r_row * DEG_CAP;
            const ushort4* l4 = g_ovf + (size_t)r_row * (DEG_CAP / 4);

            // lane-owned entries: 0-3 from header words, 4..31 from overflow
            unsigned hdr_e = (lane < 2) ? ((lane & 1) ? (w1 >> 16) : (w1 & 0xFFFFu))
                                        : ((lane & 1) ? (w2 >> 16) : (w2 & 0xFFFFu));
            unsigned e_lo = (lane < (unsigned)dg)
                                ? ((lane < 4) ? hdr_e : (unsigned)ovf[lane])
                                : (0x10000u | lane);
            unsigned m_lo = __match_any_sync(FULL, e_lo);
            bool k_lo = (lane < (unsigned)dg) &&
                        ((m_lo & ((1u << lane) - 1u)) == 0u);
            unsigned long long keep =
                (unsigned long long)__ballot_sync(FULL, k_lo);
            if (dg > 32) {                    // warp-uniform, P ~ 1e-4
                unsigned e_hi = (lane + 32 < (unsigned)dg)
                                    ? (unsigned)ovf[lane + 32]
                                    : (0x20000u | lane);
                unsigned m_hi = __match_any_sync(FULL, e_hi);
                bool k_hi = (lane + 32 < (unsigned)dg) &&
                            ((m_hi & ((1u << lane) - 1u)) == 0u);
                bool dup = false;             // cross-half duplicate test
                #pragma unroll
                for (int l = 0; l < 32; ++l) {
                    unsigned v = __shfl_sync(FULL, e_lo, l);
                    dup = dup || (v == e_hi);
                }
                k_hi = k_hi && !dup;
                keep |= ((unsigned long long)__ballot_sync(FULL, k_hi)) << 32;
            }

            // ---- gather ALL remaining quads, no intermediate ballots:
            //      every list load and gather is independent -> single
            //      latency chain for the whole row ----
            for (int k = 4; k < dg; k += 4) {
                ushort4 q = l4[k >> 2];       // uniform 8B (slots 4+ valid)
                float w0g = yb[(size_t)q.x * T + lane];
                float w1g = yb[(size_t)q.y * T + lane];
                float w2g = yb[(size_t)q.z * T + lane];
                float w3g = yb[(size_t)q.w * T + lane];
                unsigned kb = (unsigned)(keep >> k) & 0xFu;  // warp-uniform
                if (kb & 1u) accT += w0g;
                if (kb & 2u) accT += w1g;
                if (kb & 4u) accT += w2g;
                if (kb & 8u) accT += w3g;
            }

            float rr = tv ? fmaxf(ynT - accT, 0.0f) : 0.0f;
            #pragma unroll
            for (int o = 16; o > 0; o >>= 1)
                rr += __shfl_down_sync(FULL, rr, o);
            wsum += rr;                       // total lands on lane 0
        }
    }

    // block reduce (8 warps/block) -> at most one atomic per block
    __shared__ float sred[8];
    unsigned wib = threadIdx.x >> 5;
    if (lane == 0) sred[wib] = wsum;
    __syncthreads();
    if (threadIdx.x < 8) {
        float v = sred[threadIdx.x];
        #pragma unroll
        for (int o = 4; o > 0; o >>= 1)
            v += __shfl_down_sync(0x000000ffu, v, o);
        if (threadIdx.x == 0 && v != 0.0f) atomicAdd(out, v);
    }
}

// ---------------------------------------------------------------------------
// kernel_launch: build -> aggregate. Plain launches, no allocs/syncs.
// ---------------------------------------------------------------------------
extern "C" void kernel_launch(void* const* d_in, const int* in_sizes, int n_in,
                              void* d_out, int out_size) {
    (void)in_sizes; (void)n_in; (void)out_size;
    const float* y   = (const float*)d_in[0];
    const int*   coo = (const int*)d_in[1];
    float*       out = (float*)d_out;

    nil_build_kernel<<<(BS * E / 2) / 256, 256>>>(coo, out);
    // 32768 rows / 4 rows per warp / 8 warps per block = 1024 blocks
    nil_agg_kernel<<<NROWS / 32, 256>>>(y, out);
}

// round 15
// speedup vs baseline: 1.1117x; 1.1117x over previous
#include <cuda_runtime.h>
#include <cstdint>

// Problem constants (fixed by setup_inputs)
#define BS 8
#define M  4096
#define T  32
#define E  65536
#define NROWS (BS * M)          // 32768
#define DEG_CAP 64              // Poisson(16) row degree; P(>64) ~ 1e-20

// Scratch. Device globals start zeroed at module load; agg resets the header
// counts after consuming them, so every replay starts clean. Stale entry
// bytes are never read as live data (keep-mask bits beyond deg are zero) and
// are always < M, so gathers stay in-bounds.
//
// Per-row 16B header: {u32 cnt; u16 e0,e1,e2,e3; 4B pad} -> one LDG.128 in
// agg yields count + the whole fast-path quad. Entries pos >= 4 go to the
// overflow array at [row*64 + pos] (first 4 slots of each ovf row unused).
__device__ uint4   g_rec[NROWS];                 // headers (512 KB)
__device__ ushort4 g_ovf[NROWS * (DEG_CAP / 4)]; // overflow lists (4 MB)

__device__ __forceinline__ void add4(float4& a, const float4& v) {
    a.x += v.x; a.y += v.y; a.z += v.z; a.w += v.w;
}

// ---------------------------------------------------------------------------
// Kernel 1: append every edge (dups included -> dedup lazily in agg). ONE
// atomic per edge, 2 edges per thread (independent chains, MLP=2).
// A_coo is int32, layout (bs, 2, E) row-major; int2 loads from both streams.
// ---------------------------------------------------------------------------
__global__ void nil_build_kernel(const int* __restrict__ coo,
                                 float* __restrict__ out) {
    unsigned tid = blockIdx.x * blockDim.x + threadIdx.x;  // < BS*E/2
    if (tid == 0) *out = 0.0f;
    unsigned b  = tid >> 15;               // / (E/2)
    unsigned e2 = tid & (E / 2 - 1);       // edge-pair index within batch

    const int2* srcs = reinterpret_cast<const int2*>(coo + (size_t)b * 2 * E);
    const int2* tgts = reinterpret_cast<const int2*>(coo + (size_t)b * 2 * E + E);
    int2 sp = srcs[e2];
    int2 tp = tgts[e2];

    unsigned* cnts = reinterpret_cast<unsigned*>(g_rec);  // cnt @ idx row*4
    unsigned short* hdr = reinterpret_cast<unsigned short*>(g_rec);
    unsigned short* ovf = reinterpret_cast<unsigned short*>(g_ovf);

    unsigned src[2] = {(unsigned)sp.x & (M - 1), (unsigned)sp.y & (M - 1)};
    unsigned tgt[2] = {(unsigned)tp.x & (M - 1), (unsigned)tp.y & (M - 1)};
    unsigned row[2] = {b * M + src[0], b * M + src[1]};
    unsigned pos[2];
    #pragma unroll
    for (int p = 0; p < 2; ++p)            // independent chains back-to-back
        pos[p] = atomicAdd(&cnts[row[p] * 4], 1u);
    #pragma unroll
    for (int p = 0; p < 2; ++p) {
        if (pos[p] < 4)
            hdr[row[p] * 8 + 2 + pos[p]] = (unsigned short)tgt[p];
        else if (pos[p] < DEG_CAP)
            ovf[row[p] * DEG_CAP + pos[p]] = (unsigned short)tgt[p];
    }
}

// ---------------------------------------------------------------------------
// Kernel 2: one warp per FOUR consecutive rows. Lane l = (group g=l/8 -> row
// 4w+g, chunk c=l%8 -> t in [4c,4c+3]) holding acc as float4.
//   acc[t] = yb[b,i,t] (identity) + sum over DISTINCT listed targets j of
//            yb[b,j,t]  (first occurrence wins == jnp .at[].set(1.0))
//   reg   += relu(yb[b,i,t+1] - acc[t]), t in [0,31)
// Fast path: ONE 16B header load gives count + first 4 entries; rows whose
// lanes all satisfy acc >= ynext contribute EXACTLY 0 (y >= 0 -> acc
// monotone) and are done. Live rows (~4%) take a warp-converged slow path:
// transpose acc AND self to lane=t layout (registers only), build a 64-bit
// first-occurrence keep mask once via match_any, then gather TWO quads per
// early-exit check (half the ballots / half the serial chain depth of R12).
// ---------------------------------------------------------------------------
__global__ void nil_agg_kernel(const float* __restrict__ y,
                               float* __restrict__ out) {
    const unsigned FULL = 0xffffffffu;
    unsigned warp = (blockIdx.x * blockDim.x + threadIdx.x) >> 5; // 0..8191
    unsigned lane = threadIdx.x & 31;
    unsigned g = lane >> 3, c = lane & 7;

    unsigned row0 = warp << 2;        // 4 consecutive rows, same batch (M%4==0)
    unsigned row  = row0 + g;
    unsigned b    = row0 >> 12;       // / M
    const float*  yb  = y + (size_t)b * (M * T);
    const float4* yb4 = reinterpret_cast<const float4*>(yb);

    // ---- front-issue independent loads ----
    uint4 rec = g_rec[row];                            // 16B header, 64B/warp
    float4 self4 = yb4[(size_t)(row & (M - 1)) * (T / 4) + c]; // 512B coalesced

    if (lane < 4)                                      // self-clean counts
        reinterpret_cast<unsigned*>(g_rec)[(row0 + lane) * 4] = 0u;

    int deg = (int)rec.x;
    if (deg > DEG_CAP) deg = DEG_CAP;

    float4 acc = self4;                       // identity term
    // ynext for t=4c..4c+3: (self.y, self.z, self.w, next-lane self.x);
    // c==7's 4th term (t=31) is invalid and masked below.
    float n3 = __shfl_down_sync(FULL, self4.x, 1);

    // ---- quad 0 from header: 4 gathers, one LDG.128 per lane ----
    {
        unsigned e0 = rec.y & 0xFFFFu, e1 = rec.y >> 16;
        unsigned e2 = rec.z & 0xFFFFu, e3 = rec.z >> 16;
        float4 v0 = yb4[e0 * (T / 4) + c];
        float4 v1 = yb4[e1 * (T / 4) + c];
        float4 v2 = yb4[e2 * (T / 4) + c];
        float4 v3 = yb4[e3 * (T / 4) + c];
        bool u1 = (e1 != e0);
        bool u2 = (e2 != e0) & (e2 != e1);
        bool u3 = (e3 != e0) & (e3 != e1) & (e3 != e2);
        if (deg > 0)       add4(acc, v0);
        if (deg > 1 && u1) add4(acc, v1);
        if (deg > 2 && u2) add4(acc, v2);
        if (deg > 3 && u3) add4(acc, v3);
    }

    // ---- liveness: any t in this lane with acc[t] < ynext[t]? ----
    bool live = (acc.x < self4.y) | (acc.y < self4.z) | (acc.z < self4.w) |
                ((c < 7) & (acc.w < n3));
    unsigned pend = __ballot_sync(FULL, live);

    float wsum = 0.0f;                        // meaningful on lane 0 only
    if (pend) {
        // ---- warp-converged slow path, one live row at a time ----
        #pragma unroll
        for (int gg = 0; gg < 4; ++gg) {
            if (!((pend >> (8 * gg)) & 0xFFu)) continue;
            unsigned r_row = row0 + gg;
            unsigned srcw = gg * 8;
            int dg = __shfl_sync(FULL, deg, srcw);
            unsigned w1 = __shfl_sync(FULL, rec.y, srcw);
            unsigned w2 = __shfl_sync(FULL, rec.z, srcw);

            // transpose this row's acc AND self into lane=t layout (regs only)
            unsigned srcl = srcw + (lane >> 2);
            float a0 = __shfl_sync(FULL, acc.x, srcl);
            float a1 = __shfl_sync(FULL, acc.y, srcl);
            float a2 = __shfl_sync(FULL, acc.z, srcl);
            float a3 = __shfl_sync(FULL, acc.w, srcl);
            float s0 = __shfl_sync(FULL, self4.x, srcl);
            float s1 = __shfl_sync(FULL, self4.y, srcl);
            float s2 = __shfl_sync(FULL, self4.z, srcl);
            float s3 = __shfl_sync(FULL, self4.w, srcl);
            unsigned sel = lane & 3;
            float accT  = (sel == 0) ? a0 : (sel == 1) ? a1
                        : (sel == 2) ? a2 : a3;
            float selfT = (sel == 0) ? s0 : (sel == 1) ? s1
                        : (sel == 2) ? s2 : s3;
            float ynT = __shfl_down_sync(FULL, selfT, 1);
            bool tv = (lane < 31);

            const unsigned short* ovf =
                reinterpret_cast<const unsigned short*>(g_ovf) +
                (size_t)r_row * DEG_CAP;
            const ushort4* l4 = g_ovf + (size_t)r_row * (DEG_CAP / 4);

            // lane-owned entries: 0-3 from header words, 4..31 from overflow
            unsigned hdr_e = (lane < 2) ? ((lane & 1) ? (w1 >> 16) : (w1 & 0xFFFFu))
                                        : ((lane & 1) ? (w2 >> 16) : (w2 & 0xFFFFu));
            unsigned e_lo = (lane < (unsigned)dg)
                                ? ((lane < 4) ? hdr_e : (unsigned)ovf[lane])
                                : (0x10000u | lane);
            unsigned m_lo = __match_any_sync(FULL, e_lo);
            bool k_lo = (lane < (unsigned)dg) &&
                        ((m_lo & ((1u << lane) - 1u)) == 0u);
            unsigned long long keep =
                (unsigned long long)__ballot_sync(FULL, k_lo);
            if (dg > 32) {                    // warp-uniform, P ~ 1e-4
                unsigned e_hi = (lane + 32 < (unsigned)dg)
                                    ? (unsigned)ovf[lane + 32]
                                    : (0x20000u | lane);
                unsigned m_hi = __match_any_sync(FULL, e_hi);
                bool k_hi = (lane + 32 < (unsigned)dg) &&
                            ((m_hi & ((1u << lane) - 1u)) == 0u);
                bool dup = false;             // cross-half duplicate test
                #pragma unroll
                for (int l = 0; l < 32; ++l) {
                    unsigned v = __shfl_sync(FULL, e_lo, l);
                    dup = dup || (v == e_hi);
                }
                k_hi = k_hi && !dup;
                keep |= ((unsigned long long)__ballot_sync(FULL, k_hi)) << 32;
            }

            // ---- TWO quads (8 entries) per early-exit check. Both quad
            //      loads + all 8 gathers are independent; keep bits beyond
            //      dg are zero, so no per-element bounds checks needed. ----
            unsigned pnd = __ballot_sync(FULL, tv && accT < ynT);
            for (int k = 4; k < dg && pnd; k += 8) {
                unsigned qa_i = (unsigned)(k >> 2);
                unsigned qb_i = qa_i + 1u;
                if (qb_i > 15u) qb_i = 15u;   // clamp: stay inside this row
                ushort4 qa = l4[qa_i];
                ushort4 qb = l4[qb_i];
                float g0 = yb[(size_t)qa.x * T + lane];
                float g1 = yb[(size_t)qa.y * T + lane];
                float g2 = yb[(size_t)qa.z * T + lane];
                float g3 = yb[(size_t)qa.w * T + lane];
                float g4 = yb[(size_t)qb.x * T + lane];
                float g5 = yb[(size_t)qb.y * T + lane];
                float g6 = yb[(size_t)qb.z * T + lane];
                float g7 = yb[(size_t)qb.w * T + lane];
                unsigned kb = (unsigned)(keep >> k) & 0xFFu;  // warp-uniform
                if (kb & 0x01u) accT += g0;
                if (kb & 0x02u) accT += g1;
                if (kb & 0x04u) accT += g2;
                if (kb & 0x08u) accT += g3;
                if (kb & 0x10u) accT += g4;
                if (kb & 0x20u) accT += g5;
                if (kb & 0x40u) accT += g6;
                if (kb & 0x80u) accT += g7;
                pnd = __ballot_sync(FULL, tv && accT < ynT);
            }
            if (pnd) {
                float rr = tv ? fmaxf(ynT - accT, 0.0f) : 0.0f;
                #pragma unroll
                for (int o = 16; o > 0; o >>= 1)
                    rr += __shfl_down_sync(FULL, rr, o);
                wsum += rr;                   // total lands on lane 0
            }
        }
    }

    // block reduce (8 warps/block) -> at most one atomic per block
    __shared__ float sred[8];
    unsigned wib = threadIdx.x >> 5;
    if (lane == 0) sred[wib] = wsum;
    __syncthreads();
    if (threadIdx.x < 8) {
        float v = sred[threadIdx.x];
        #pragma unroll
        for (int o = 4; o > 0; o >>= 1)
            v += __shfl_down_sync(0x000000ffu, v, o);
        if (threadIdx.x == 0 && v != 0.0f) atomicAdd(out, v);
    }
}

// ---------------------------------------------------------------------------
// kernel_launch: build -> aggregate. Plain launches, no allocs/syncs.
// ---------------------------------------------------------------------------
extern "C" void kernel_launch(void* const* d_in, const int* in_sizes, int n_in,
                              void* d_out, int out_size) {
    (void)in_sizes; (void)n_in; (void)out_size;
    const float* y   = (const float*)d_in[0];
    const int*   coo = (const int*)d_in[1];
    float*       out = (float*)d_out;

    nil_build_kernel<<<(BS * E / 2) / 256, 256>>>(coo, out);
    // 32768 rows / 4 rows per warp / 8 warps per block = 1024 blocks
    nil_agg_kernel<<<NROWS / 32, 256>>>(y, out);
}